// round 3
// baseline (speedup 1.0000x reference)
#include <cuda_runtime.h>
#include <cuda_pipeline.h>
#include <mma.h>
#include <cstdint>

using namespace nvcuda;

namespace {
constexpr int BATCH = 8;
constexpr int CH    = 1024;
constexpr int P     = 48 * 48;     // 2304
constexpr int PD    = 24;
constexpr int PI    = PD * PD;     // 576
constexpr int S     = PI * PI;     // 331776
constexpr float EPS_L2 = 1e-6f;
constexpr float EPS_MM = 1e-5f;
}

__device__ float g_inva[BATCH * P];
__device__ float g_invb[BATCH * P];
__device__ float g_pool[(size_t)BATCH * S];
__device__ float g_x0  [(size_t)BATCH * S];
__device__ float g_y1  [(size_t)BATCH * 10 * S];
__device__ float g_y2  [(size_t)BATCH * 10 * S];
__device__ float g_y3  [(size_t)BATCH * S];
__device__ float g_rmax[BATCH * PI];
__device__ float g_cmax[BATCH * PI];

// ---- per-position inverse L2 norms ----
__global__ void norm_kernel(const float* __restrict__ fa, const float* __restrict__ fb) {
    int idx = blockIdx.x * blockDim.x + threadIdx.x;
    int b = idx / P, p = idx - b * P;
    const float* a  = fa + (size_t)b * CH * P + p;
    const float* bb = fb + (size_t)b * CH * P + p;
    float sa = 0.f, sb = 0.f;
#pragma unroll 8
    for (int c = 0; c < CH; c++) {
        float x = a[(size_t)c * P];  sa = fmaf(x, x, sa);
        float y = bb[(size_t)c * P]; sb = fmaf(y, y, sb);
    }
    g_inva[idx] = rsqrtf(sa + EPS_L2);
    g_invb[idx] = rsqrtf(sb + EPS_L2);
}

__global__ void zero_pool_kernel() {
    size_t i = (size_t)blockIdx.x * blockDim.x + threadIdx.x;
    g_pool[i] = 0.f;
    if (i < BATCH * PI) g_cmax[i] = 0.f;
}

// ---- correlation GEMM (tf32 wmma) + fused norm/relu/L2/pool epilogue ----
__global__ void __launch_bounds__(256)
corr_kernel(const float* __restrict__ fa, const float* __restrict__ fb) {
    __shared__ __align__(16) float As[2][16][132];
    __shared__ __align__(16) float Bs[2][16][132];
    __shared__ float wbuf[8][256];

    const int b  = blockIdx.z;
    const float* Ag = fa + (size_t)b * CH * P;
    const float* Bg = fb + (size_t)b * CH * P;
    const int m0 = blockIdx.x * 128, n0 = blockIdx.y * 128;
    const int tid = threadIdx.x, wid = tid >> 5, lane = tid & 31;
    const int wm = wid >> 2, wn = wid & 3;   // 64(m) x 32(n) per warp

    wmma::fragment<wmma::accumulator, 16, 16, 8, float> acc[4][2];
#pragma unroll
    for (int i = 0; i < 4; i++)
#pragma unroll
        for (int j = 0; j < 2; j++) wmma::fill_fragment(acc[i][j], 0.0f);

    auto load_tile = [&](int kt, int buf) {
        const int k0 = kt * 16;
#pragma unroll
        for (int v = 0; v < 2; v++) {
            int l = tid + v * 256;
            int r = l >> 5, c = (l & 31) << 2;
            __pipeline_memcpy_async(&As[buf][r][c], Ag + (size_t)(k0 + r) * P + m0 + c, 16);
            __pipeline_memcpy_async(&Bs[buf][r][c], Bg + (size_t)(k0 + r) * P + n0 + c, 16);
        }
        __pipeline_commit();
    };

    load_tile(0, 0);
    const int NT = CH / 16;
    for (int kt = 0; kt < NT; kt++) {
        if (kt + 1 < NT) load_tile(kt + 1, (kt + 1) & 1);
        __pipeline_wait_prior((kt + 1 < NT) ? 1 : 0);
        __syncthreads();
        const int buf = kt & 1;
#pragma unroll
        for (int ks = 0; ks < 2; ks++) {
            const int kk = ks * 8;
            wmma::fragment<wmma::matrix_a, 16, 16, 8, wmma::precision::tf32, wmma::col_major> af[4];
            wmma::fragment<wmma::matrix_b, 16, 16, 8, wmma::precision::tf32, wmma::row_major> bf[2];
#pragma unroll
            for (int i = 0; i < 4; i++) {
                wmma::load_matrix_sync(af[i], &As[buf][kk][wm * 64 + i * 16], 132);
#pragma unroll
                for (int t = 0; t < af[i].num_elements; t++)
                    af[i].x[t] = wmma::__float_to_tf32(af[i].x[t]);
            }
#pragma unroll
            for (int j = 0; j < 2; j++) {
                wmma::load_matrix_sync(bf[j], &Bs[buf][kk][wn * 32 + j * 16], 132);
#pragma unroll
                for (int t = 0; t < bf[j].num_elements; t++)
                    bf[j].x[t] = wmma::__float_to_tf32(bf[j].x[t]);
            }
#pragma unroll
            for (int i = 0; i < 4; i++)
#pragma unroll
                for (int j = 0; j < 2; j++)
                    wmma::mma_sync(acc[i][j], af[i], bf[j], acc[i][j]);
        }
        __syncthreads();
    }

#pragma unroll 1
    for (int i = 0; i < 4; i++) {
#pragma unroll 1
        for (int j = 0; j < 2; j++) {
            wmma::store_matrix_sync(&wbuf[wid][0], acc[i][j], 16, wmma::mem_row_major);
            __syncwarp();
            const int tm0 = m0 + wm * 64 + i * 16;
            const int tn0 = n0 + wn * 32 + j * 16;
            const int row = lane >> 1;
            const int cb  = (lane & 1) * 8;
            const int p   = tm0 + row;
            const float ia = g_inva[b * P + p];
            float v[8];
#pragma unroll
            for (int c = 0; c < 8; c++) {
                int q = tn0 + cb + c;
                float raw = wbuf[wid][row * 16 + cb + c] * ia * g_invb[b * P + q];
                raw = fmaxf(raw, 0.f);
                v[c] = raw * rsqrtf(raw * raw + EPS_L2);
            }
            float c2[4];
#pragma unroll
            for (int u = 0; u < 4; u++) c2[u] = fmaxf(v[2 * u], v[2 * u + 1]);
#pragma unroll
            for (int u = 0; u < 4; u++)
                c2[u] = fmaxf(c2[u], __shfl_xor_sync(0xffffffffu, c2[u], 2));
            if ((lane & 2) == 0) {
                const int PA = ((p / 48) >> 1) * 24 + ((p % 48) >> 1);
                float* poolb = g_pool + (size_t)b * S + (size_t)PA * PI;
#pragma unroll
                for (int u = 0; u < 4; u++) {
                    int q  = tn0 + cb + 2 * u;
                    int PB = ((q / 48) >> 1) * 24 + ((q % 48) >> 1);
                    atomicMax(reinterpret_cast<int*>(&poolb[PB]), __float_as_int(c2[u]));
                }
            }
            __syncwarp();
        }
    }
}

// ---- mutual matching ----
__global__ void rowmax_kernel(int which) {
    const float* x = (which == 0) ? g_pool : g_y3;
    int row  = blockIdx.x * 8 + (threadIdx.x >> 5);
    int lane = threadIdx.x & 31;
    const float* xr = x + (size_t)row * PI;
    float m = 0.f;
    for (int j = lane; j < PI; j += 32) m = fmaxf(m, xr[j]);
#pragma unroll
    for (int o = 16; o; o >>= 1) m = fmaxf(m, __shfl_xor_sync(0xffffffffu, m, o));
    if (lane == 0) g_rmax[row] = m;
}

__global__ void colmax_kernel(int which) {  // grid (8,16), 576 thr
    const float* x = (which == 0) ? g_pool : g_y3;
    int b = blockIdx.x, j = threadIdx.x;
    const float* xb = x + (size_t)b * S;
    int i0 = blockIdx.y * 36;
    float m = 0.f;
    for (int i = i0; i < i0 + 36; i++) m = fmaxf(m, xb[(size_t)i * PI + j]);
    atomicMax(reinterpret_cast<int*>(&g_cmax[b * PI + j]), __float_as_int(m));
}

__global__ void mm_apply_kernel(int which, float* __restrict__ outp) {
    int idx = blockIdx.x * blockDim.x + threadIdx.x;
    int b = idx / S, rem = idx - b * S;
    int i = rem / PI, j = rem - i * PI;
    const float* x = which ? g_y3 : g_pool;
    float* dst = which ? outp : g_x0;
    float v  = x[idx];
    dst[idx] = v * (v / (g_rmax[b * PI + i] + EPS_MM)) * (v / (g_cmax[b * PI + j] + EPS_MM));
}

// ---- Conv4d 3^4 SAME, direct fp32 ----
template <int CI, int CO>
__global__ void __launch_bounds__(256)
conv_kernel(const float* __restrict__ x, float* __restrict__ y,
            const float* __restrict__ w, const float* __restrict__ bias) {
    __shared__ float ws[81 * CI * CO];
    __shared__ float bs[CO];
    for (int l = threadIdx.x; l < 81 * CI * CO; l += blockDim.x) {
        int tap = l / (CI * CO), r = l - tap * (CI * CO);
        int ci = r / CO, co = r - ci * CO;
        ws[l] = w[(co * CI + ci) * 81 + tap];
    }
    if (threadIdx.x < CO) bs[threadIdx.x] = bias[threadIdx.x];
    __syncthreads();
    int idx = blockIdx.x * blockDim.x + threadIdx.x;
    int b = idx / S, s = idx - b * S;
    int d4 = s % 24, t = s / 24;
    int d3 = t % 24; t /= 24;
    int d2 = t % 24, d1 = t / 24;
    const float* xb = x + (size_t)b * CI * S;
    float acc[CO];
#pragma unroll
    for (int co = 0; co < CO; co++) acc[co] = 0.f;
#pragma unroll 1
    for (int t1 = 0; t1 < 3; t1++) {
        int e1 = d1 + t1 - 1; if ((unsigned)e1 >= 24u) continue;
#pragma unroll 1
        for (int t2 = 0; t2 < 3; t2++) {
            int e2 = d2 + t2 - 1; if ((unsigned)e2 >= 24u) continue;
#pragma unroll 1
            for (int t3 = 0; t3 < 3; t3++) {
                int e3 = d3 + t3 - 1; if ((unsigned)e3 >= 24u) continue;
                int spb  = ((e1 * 24 + e2) * 24 + e3) * 24;
                int tapb = ((t1 * 3 + t2) * 3 + t3) * 3;
#pragma unroll 1
                for (int t4 = 0; t4 < 3; t4++) {
                    int e4 = d4 + t4 - 1; if ((unsigned)e4 >= 24u) continue;
                    int sp = spb + e4, tap = tapb + t4;
#pragma unroll
                    for (int ci = 0; ci < CI; ci++) {
                        float xv = xb[(size_t)ci * S + sp];
                        const float* wp = &ws[(tap * CI + ci) * CO];
#pragma unroll
                        for (int co = 0; co < CO; co++) acc[co] = fmaf(xv, wp[co], acc[co]);
                    }
                }
            }
        }
    }
#pragma unroll
    for (int co = 0; co < CO; co++)
        y[((size_t)b * CO + co) * S + s] = fmaxf(acc[co] + bs[co], 0.f);
}

extern "C" void kernel_launch(void* const* d_in, const int* in_sizes, int n_in,
                              void* d_out, int out_size) {
    const float* fa = (const float*)d_in[0];
    const float* fb = (const float*)d_in[1];
    const float* w1 = (const float*)d_in[2];
    const float* b1 = (const float*)d_in[3];
    const float* w2 = (const float*)d_in[4];
    const float* b2 = (const float*)d_in[5];
    const float* w3 = (const float*)d_in[6];
    const float* b3 = (const float*)d_in[7];
    float* out = (float*)d_out;

    float *p_x0, *p_y1, *p_y2, *p_y3;
    cudaGetSymbolAddress((void**)&p_x0, g_x0);
    cudaGetSymbolAddress((void**)&p_y1, g_y1);
    cudaGetSymbolAddress((void**)&p_y2, g_y2);
    cudaGetSymbolAddress((void**)&p_y3, g_y3);

    const int NS = BATCH * S / 256;   // 10368
    norm_kernel<<<BATCH * P / 256, 256>>>(fa, fb);
    zero_pool_kernel<<<NS, 256>>>();
    dim3 cg(18, 18, 8);
    corr_kernel<<<cg, 256>>>(fa, fb);

    rowmax_kernel<<<BATCH * PI / 8, 256>>>(0);
    colmax_kernel<<<dim3(8, 16), PI>>>(0);
    mm_apply_kernel<<<NS, 256>>>(0, nullptr);

    conv_kernel<1, 10><<<NS, 256>>>(p_x0, p_y1, w1, b1);
    conv_kernel<10, 10><<<NS, 256>>>(p_y1, p_y2, w2, b2);
    conv_kernel<10, 1><<<NS, 256>>>(p_y2, p_y3, w3, b3);

    zero_pool_kernel<<<NS, 256>>>();   // re-zero g_cmax (g_pool unused after)
    rowmax_kernel<<<BATCH * PI / 8, 256>>>(1);
    colmax_kernel<<<dim3(8, 16), PI>>>(1);
    mm_apply_kernel<<<NS, 256>>>(1, out);
}